// round 7
// baseline (speedup 1.0000x reference)
#include <cuda_runtime.h>
#include <cstdint>

// Problem dims (fixed)
#define BATCH 16384
#define DIM   1024

// ---- tcgen05 GEMM tiling ----
#define BM2 256            // M rows per CTA (two M=128 MMAs)
#define BN2 256            // N cols per CTA (one N=256 MMA)
#define BK2 32             // K floats per tile (128 bytes = SW128 row)
#define NT  32             // 1024 / 32 k-tiles
#define STAGES 3
#define ASZ 32768          // 256 rows * 128B
#define BSZ 32768          // 256 rows * 128B
#define A_OFF 1024
#define B_OFF (A_OFF + STAGES * ASZ)
#define GEMM_SMEM (B_OFF + STAGES * BSZ)    // 197632 B
#define MBAR_OFF 16

// idesc: D=F32(1<<4), A=TF32(2<<7), B=TF32(2<<10), N=256 (32<<17), M=128 (8<<24)
#define IDESC_TF32 ((1u<<4) | (2u<<7) | (2u<<10) | (32u<<17) | (8u<<24))

// Scratch (device globals — allocation-free)
__device__ float g_xk[BATCH * DIM];
__device__ float g_xv[BATCH * DIM];
__device__ float g_xr[BATCH * DIM];
__device__ float g_K[BATCH * DIM];
__device__ float g_V[BATCH * DIM];
__device__ float g_R[BATCH * DIM];
__device__ float g_rwkv[BATCH * DIM];
__device__ float g_Wt[4 * DIM * DIM];   // tf32, TRANSPOSED: [N, K] K-major

// ---------------------------------------------------------------------------
// helpers (arch-portable)
// ---------------------------------------------------------------------------
__device__ __forceinline__ float tf32_rna(float x) {
    unsigned u;
    asm("cvt.rna.tf32.f32 %0, %1;" : "=r"(u) : "f"(x));
    return __uint_as_float(u);
}
__device__ __forceinline__ uint32_t smem_u32(const void* p) {
    return (uint32_t)__cvta_generic_to_shared(p);
}
__device__ __forceinline__ void cp_async16(uint32_t smem_addr, const void* gmem_ptr) {
    asm volatile("cp.async.cg.shared.global [%0], [%1], 16;\n" :: "r"(smem_addr), "l"(gmem_ptr));
}
__device__ __forceinline__ void cp_commit() { asm volatile("cp.async.commit_group;\n"); }
template <int N> __device__ __forceinline__ void cp_wait() {
    asm volatile("cp.async.wait_group %0;\n" :: "n"(N));
}
__device__ __forceinline__ void mbar_init(uint32_t a, uint32_t cnt) {
    asm volatile("mbarrier.init.shared.b64 [%0], %1;" :: "r"(a), "r"(cnt) : "memory");
}
__device__ __forceinline__ void mbar_wait(uint32_t a, uint32_t parity) {
    asm volatile(
        "{\n\t.reg .pred P;\n"
        "WL%=:\n\t"
        "mbarrier.try_wait.parity.acquire.cta.shared::cta.b64 P, [%0], %1, 0x989680;\n\t"
        "@P bra WD%=;\n\t"
        "bra WL%=;\n"
        "WD%=:\n\t}"
        :: "r"(a), "r"(parity) : "memory");
}

// ---------------------------------------------------------------------------
// tcgen05 helpers — sm_103a ONLY (guarded so the generic compute_103 PTX pass
// never sees tcgen05 instructions; the sm_103a cubin carries the real code)
// ---------------------------------------------------------------------------
#if defined(__CUDA_ARCH_FEAT_SM103_ALL) || defined(__CUDA_ARCH_FEAT_SM100_ALL)
#define HAS_TCGEN05 1
#else
#define HAS_TCGEN05 0
#endif

#if HAS_TCGEN05
__device__ __forceinline__ uint32_t elect_one() {
    uint32_t p;
    asm volatile("{\n.reg .pred P;\nelect.sync _|P, 0xFFFFFFFF;\nselp.b32 %0, 1, 0, P;\n}" : "=r"(p));
    return p;
}
// 64-bit smem descriptor: SW128, version=1 (Blackwell), LBO=1, SBO=64 (K-major)
__device__ __forceinline__ uint64_t make_desc(uint32_t addr) {
    const uint64_t base = (uint64_t(2) << 61) | (uint64_t(1) << 46)
                        | (uint64_t(64) << 32) | (uint64_t(1) << 16);
    return base | ((uint64_t)(addr >> 4) & 0x3FFF);
}
__device__ __forceinline__ void mma_tf32_ss(uint32_t d, uint64_t ad, uint64_t bd,
                                            uint32_t idesc, uint32_t en) {
    asm volatile(
        "{\n\t.reg .pred p;\n\t"
        "setp.ne.u32 p, %5, 0;\n\t"
        "tcgen05.mma.cta_group::1.kind::tf32 [%0], %1, %2, %3, {%4, %4, %4, %4}, p;\n\t}"
        :: "r"(d), "l"(ad), "l"(bd), "r"(idesc), "r"(0u), "r"(en) : "memory");
}
__device__ __forceinline__ void tc_commit(uint32_t mbar) {
    asm volatile(
        "tcgen05.commit.cta_group::1.mbarrier::arrive::one.shared::cluster.b64 [%0];"
        :: "r"(mbar) : "memory");
}
#endif

// ---------------------------------------------------------------------------
// tcgen05 tf32 GEMM: C[B*, 1024] = A[B*, 1024] @ Wt^T   (Wt is [N,K] K-major)
// CTA computes 256x256 tile. blockIdx.z selects A/B/C triple.
// ---------------------------------------------------------------------------
__global__ void __launch_bounds__(256, 1)
gemm_tc_kernel(const float* __restrict__ A0, const float* __restrict__ A1,
               const float* __restrict__ A2,
               const float* __restrict__ B0, const float* __restrict__ B1,
               const float* __restrict__ B2,
               float* __restrict__ C0, float* __restrict__ C1,
               float* __restrict__ C2)
{
#if HAS_TCGEN05
    const float* A;
    const float* B;
    float* C;
    if (blockIdx.z == 0)      { A = A0; B = B0; C = C0; }
    else if (blockIdx.z == 1) { A = A1; B = B1; C = C1; }
    else                      { A = A2; B = B2; C = C2; }

    extern __shared__ char smem[];
    const uint32_t sb = smem_u32(smem);

    const int tid = threadIdx.x;
    const int row0 = blockIdx.y * BM2;
    const int col0 = blockIdx.x * BN2;

    // TMEM alloc (512 cols): warp 0, collective
    if (tid < 32) {
        asm volatile("tcgen05.alloc.cta_group::1.sync.aligned.shared::cta.b32 [%0], %1;"
                     :: "r"(sb), "r"(512u) : "memory");
    }
    if (tid == 0) {
#pragma unroll
        for (int s = 0; s < STAGES; s++) mbar_init(sb + MBAR_OFF + s * 16, 1);
    }
    __syncthreads();
    uint32_t tmem;
    asm volatile("ld.shared.b32 %0, [%1];" : "=r"(tmem) : "r"(sb));

    // ---- tile loader: A 256x32f, B 256x32f, SW128 swizzle, cp.async 16B ----
    auto load_tile = [&](int t, int stage) {
        const int k0 = t * BK2;
        const uint32_t as = sb + A_OFF + stage * ASZ;
        const uint32_t bs = sb + B_OFF + stage * BSZ;
#pragma unroll
        for (int j = 0; j < 8; j++) {
            int i = tid + 256 * j;          // 0..2047
            int row = i >> 3, c = i & 7;
            cp_async16(as + row * 128 + ((c ^ (row & 7)) << 4),
                       A + (long)(row0 + row) * DIM + k0 + c * 4);
        }
#pragma unroll
        for (int j = 0; j < 8; j++) {
            int i = tid + 256 * j;
            int row = i >> 3, c = i & 7;
            cp_async16(bs + row * 128 + ((c ^ (row & 7)) << 4),
                       B + (long)(col0 + row) * DIM + k0 + c * 4);
        }
        cp_commit();
    };

    // prologue: tiles 0, 1
    load_tile(0, 0);
    load_tile(1, 1);

    for (int u = 0; u < NT; u++) {
        // tile u ready
        if (u == NT - 1) cp_wait<0>(); else cp_wait<1>();
        __syncthreads();

        // MMA issue (warp 0 elect)
        if (tid < 32) {
            asm volatile("fence.proxy.async.shared::cta;" ::: "memory");
            if (elect_one()) {
                const int st = u % STAGES;
                uint64_t ad0 = make_desc(sb + A_OFF + st * ASZ);
                uint64_t ad1 = make_desc(sb + A_OFF + st * ASZ + 16384);
                uint64_t bd  = make_desc(sb + B_OFF + st * BSZ);
#pragma unroll
                for (int ks = 0; ks < 4; ks++) {
                    uint32_t en = (u == 0 && ks == 0) ? 0u : 1u;
                    mma_tf32_ss(tmem,        ad0 + ks * 2, bd + ks * 2, IDESC_TF32, en);
                    mma_tf32_ss(tmem + 256,  ad1 + ks * 2, bd + ks * 2, IDESC_TF32, en);
                }
                tc_commit(sb + MBAR_OFF + st * 16);
            }
        }

        // prefetch tile u+2 into stage (u+2)%3 (freed by MMA of tile u-1)
        if (u + 2 < NT) {
            if (u >= 1) {
                const int t = u - 1;
                mbar_wait(sb + MBAR_OFF + (t % STAGES) * 16, (uint32_t)((t / STAGES) & 1));
            }
            load_tile(u + 2, (u + 2) % STAGES);
        }
    }

    // wait for final MMA (tile NT-1)
    mbar_wait(sb + MBAR_OFF + ((NT - 1) % STAGES) * 16, (uint32_t)(((NT - 1) / STAGES) & 1));
    asm volatile("tcgen05.fence::after_thread_sync;" ::: "memory");

    // ---- epilogue: 8 warps; warps 0-3 -> D0 (rows 0-127), 4-7 -> D1 ----
    {
        const int w = tid >> 5, lane = tid & 31;
        const uint32_t woff = (uint32_t)(w & 3) << 21;
        const uint32_t dbase = tmem + ((w >> 2) ? 256u : 0u) + woff;
        const int grow = row0 + (w >> 2) * 128 + (w & 3) * 32 + lane;
        float* crow = C + (long)grow * DIM + col0;
#pragma unroll
        for (int cb = 0; cb < 256; cb += 32) {
            uint32_t r[32];
            asm volatile(
                "tcgen05.ld.sync.aligned.32x32b.x32.b32 "
                "{%0,%1,%2,%3,%4,%5,%6,%7,%8,%9,%10,%11,%12,%13,%14,%15,"
                "%16,%17,%18,%19,%20,%21,%22,%23,%24,%25,%26,%27,%28,%29,%30,%31}, [%32];"
                : "=r"(r[0]), "=r"(r[1]), "=r"(r[2]), "=r"(r[3]),
                  "=r"(r[4]), "=r"(r[5]), "=r"(r[6]), "=r"(r[7]),
                  "=r"(r[8]), "=r"(r[9]), "=r"(r[10]), "=r"(r[11]),
                  "=r"(r[12]), "=r"(r[13]), "=r"(r[14]), "=r"(r[15]),
                  "=r"(r[16]), "=r"(r[17]), "=r"(r[18]), "=r"(r[19]),
                  "=r"(r[20]), "=r"(r[21]), "=r"(r[22]), "=r"(r[23]),
                  "=r"(r[24]), "=r"(r[25]), "=r"(r[26]), "=r"(r[27]),
                  "=r"(r[28]), "=r"(r[29]), "=r"(r[30]), "=r"(r[31])
                : "r"(dbase + cb));
            asm volatile("tcgen05.wait::ld.sync.aligned;" ::: "memory");
#pragma unroll
            for (int j = 0; j < 32; j += 4)
                *(float4*)(crow + cb + j) =
                    make_float4(__uint_as_float(r[j]), __uint_as_float(r[j + 1]),
                                __uint_as_float(r[j + 2]), __uint_as_float(r[j + 3]));
        }
    }

    __syncthreads();
    if (tid < 32) {
        asm volatile("tcgen05.relinquish_alloc_permit.cta_group::1.sync.aligned;");
        asm volatile("tcgen05.dealloc.cta_group::1.sync.aligned.b32 %0, %1;"
                     :: "r"(tmem), "r"(512u));
    }
#endif  // HAS_TCGEN05
}

// ---------------------------------------------------------------------------
// premix: xk/xv/xr = tf32( lerp(last_x, x, mix) )
// ---------------------------------------------------------------------------
__global__ void __launch_bounds__(256)
premix_kernel(const float* __restrict__ x, const float* __restrict__ lx,
              const float* __restrict__ mk, const float* __restrict__ mv,
              const float* __restrict__ mr)
{
    const long i = ((long)blockIdx.x * 256 + threadIdx.x) * 4;
    const int c = (int)(i & (DIM - 1));
    float4 xv4 = *(const float4*)(x + i);
    float4 lv4 = *(const float4*)(lx + i);
    float4 m, o;

    m = *(const float4*)(mk + c);
    o.x = tf32_rna(fmaf(xv4.x - lv4.x, m.x, lv4.x));
    o.y = tf32_rna(fmaf(xv4.y - lv4.y, m.y, lv4.y));
    o.z = tf32_rna(fmaf(xv4.z - lv4.z, m.z, lv4.z));
    o.w = tf32_rna(fmaf(xv4.w - lv4.w, m.w, lv4.w));
    *(float4*)(g_xk + i) = o;

    m = *(const float4*)(mv + c);
    o.x = tf32_rna(fmaf(xv4.x - lv4.x, m.x, lv4.x));
    o.y = tf32_rna(fmaf(xv4.y - lv4.y, m.y, lv4.y));
    o.z = tf32_rna(fmaf(xv4.z - lv4.z, m.z, lv4.z));
    o.w = tf32_rna(fmaf(xv4.w - lv4.w, m.w, lv4.w));
    *(float4*)(g_xv + i) = o;

    m = *(const float4*)(mr + c);
    o.x = tf32_rna(fmaf(xv4.x - lv4.x, m.x, lv4.x));
    o.y = tf32_rna(fmaf(xv4.y - lv4.y, m.y, lv4.y));
    o.z = tf32_rna(fmaf(xv4.z - lv4.z, m.z, lv4.z));
    o.w = tf32_rna(fmaf(xv4.w - lv4.w, m.w, lv4.w));
    *(float4*)(g_xr + i) = o;
}

// ---------------------------------------------------------------------------
// weight convert + transpose: g_Wt[z][n*1024 + k] = tf32(W_z[k*1024 + n])
// ---------------------------------------------------------------------------
__global__ void __launch_bounds__(256)
cvtw_kernel(const float* __restrict__ Wk, const float* __restrict__ Wv,
            const float* __restrict__ Wr, const float* __restrict__ Wout)
{
    __shared__ float t[32][33];
    const float* src;
    if (blockIdx.z == 0)      src = Wk;
    else if (blockIdx.z == 1) src = Wv;
    else if (blockIdx.z == 2) src = Wr;
    else                      src = Wout;
    float* dst = g_Wt + (long)blockIdx.z * DIM * DIM;

    const int kb = blockIdx.x * 32, nb = blockIdx.y * 32;
    const int tx = threadIdx.x & 31, ty = threadIdx.x >> 5;   // 32 x 8
#pragma unroll
    for (int r = ty; r < 32; r += 8)
        t[r][tx] = tf32_rna(src[(long)(kb + r) * DIM + nb + tx]);
    __syncthreads();
#pragma unroll
    for (int r = ty; r < 32; r += 8)
        dst[(long)(nb + r) * DIM + kb + tx] = t[tx][r];
}

// ---------------------------------------------------------------------------
// elementwise RWKV recurrence
// ---------------------------------------------------------------------------
__global__ void __launch_bounds__(256)
rwkv_ew_kernel(const float* __restrict__ last_num, const float* __restrict__ last_den,
               const float* __restrict__ decay, const float* __restrict__ bonus,
               float* __restrict__ num_out, float* __restrict__ den_out)
{
    const long i = ((long)blockIdx.x * 256 + threadIdx.x) * 4;
    const int a = (int)(i & (DIM - 1));

    float4 kk = *(const float4*)(g_K + i);
    float4 vv = *(const float4*)(g_V + i);
    float4 rp = *(const float4*)(g_R + i);
    float4 ln = *(const float4*)(last_num + i);
    float4 ld = *(const float4*)(last_den + i);
    float4 bo = *(const float4*)(bonus + a);
    float4 de = *(const float4*)(decay + a);

    float4 rw, no, dn;
    {
        const float* kp = &kk.x; const float* vp = &vv.x; const float* rpp = &rp.x;
        const float* lnp = &ln.x; const float* ldp = &ld.x;
        const float* bop = &bo.x; const float* dep = &de.x;
        float* rwp = &rw.x; float* nop = &no.x; float* dnp = &dn.x;
#pragma unroll
        for (int t = 0; t < 4; t++) {
            float k = kp[t], v = vp[t];
            float ebk = expf(bop[t] + k);
            float wkv = (lnp[t] + ebk * v) / (ldp[t] + ebk);
            float r = 1.0f / (1.0f + expf(-rpp[t]));
            rwp[t] = tf32_rna(r * wkv);
            float w = expf(-expf(dep[t]));
            float ek = expf(k);
            nop[t] = w * lnp[t] + ek * v;
            dnp[t] = w * ldp[t] + ek;
        }
    }
    *(float4*)(g_rwkv + i)  = rw;
    *(float4*)(num_out + i) = no;
    *(float4*)(den_out + i) = dn;
}

// ---------------------------------------------------------------------------
// Launch
// ---------------------------------------------------------------------------
extern "C" void kernel_launch(void* const* d_in, const int* in_sizes, int n_in,
                              void* d_out, int out_size)
{
    const float* x        = (const float*)d_in[0];
    const float* last_x   = (const float*)d_in[1];
    const float* last_num = (const float*)d_in[2];
    const float* last_den = (const float*)d_in[3];
    const float* mix_k    = (const float*)d_in[4];
    const float* mix_v    = (const float*)d_in[5];
    const float* mix_r    = (const float*)d_in[6];
    const float* decay    = (const float*)d_in[7];
    const float* bonus    = (const float*)d_in[8];
    const float* Wk       = (const float*)d_in[9];
    const float* Wv       = (const float*)d_in[10];
    const float* Wr       = (const float*)d_in[11];
    const float* Wout     = (const float*)d_in[12];

    float* out = (float*)d_out;
    const long BD = (long)BATCH * DIM;
    float* hidden_out = out;
    float* x_out      = out + BD;
    float* num_out    = out + 2 * BD;
    float* den_out    = out + 3 * BD;

    static bool attr_set = false;
    if (!attr_set) {
        cudaFuncSetAttribute(gemm_tc_kernel,
                             cudaFuncAttributeMaxDynamicSharedMemorySize, GEMM_SMEM);
        attr_set = true;
    }

    float *p_xk, *p_xv, *p_xr, *p_K, *p_V, *p_R, *p_rwkv, *p_Wt;
    cudaGetSymbolAddress((void**)&p_xk, g_xk);
    cudaGetSymbolAddress((void**)&p_xv, g_xv);
    cudaGetSymbolAddress((void**)&p_xr, g_xr);
    cudaGetSymbolAddress((void**)&p_K, g_K);
    cudaGetSymbolAddress((void**)&p_V, g_V);
    cudaGetSymbolAddress((void**)&p_R, g_R);
    cudaGetSymbolAddress((void**)&p_rwkv, g_rwkv);
    cudaGetSymbolAddress((void**)&p_Wt, g_Wt);

    // 1) premix
    premix_kernel<<<(unsigned)(BD / 4 / 256), 256>>>(x, last_x, mix_k, mix_v, mix_r);

    // 2) weight convert+transpose (tiny)
    dim3 gw(DIM / 32, DIM / 32, 4);
    cvtw_kernel<<<gw, 256>>>(Wk, Wv, Wr, Wout);

    // 3) K/V/R projections
    dim3 grid1(DIM / BN2, BATCH / BM2, 3);
    gemm_tc_kernel<<<grid1, 256, GEMM_SMEM>>>(
        p_xk, p_xv, p_xr,
        p_Wt + 0L * DIM * DIM, p_Wt + 1L * DIM * DIM, p_Wt + 2L * DIM * DIM,
        p_K, p_V, p_R);

    // 4) elementwise recurrence
    rwkv_ew_kernel<<<(unsigned)(BD / 4 / 256), 256>>>(last_num, last_den, decay, bonus,
                                                      num_out, den_out);

    // 5) hidden = rwkv @ Wout
    dim3 grid2(DIM / BN2, BATCH / BM2, 1);
    gemm_tc_kernel<<<grid2, 256, GEMM_SMEM>>>(
        p_rwkv, p_rwkv, p_rwkv,
        p_Wt + 3L * DIM * DIM, p_Wt + 3L * DIM * DIM, p_Wt + 3L * DIM * DIM,
        hidden_out, hidden_out, hidden_out);

    // 6) passthrough x
    cudaMemcpyAsync(x_out, x, BD * sizeof(float), cudaMemcpyDeviceToDevice);
}

// round 8
// speedup vs baseline: 1.0669x; 1.0669x over previous
#include <cuda_runtime.h>
#include <cstdint>

// Problem dims (fixed)
#define BATCH 16384
#define DIM   1024

// ---- tcgen05 GEMM tiling ----
#define BM2 256            // M rows per CTA (two M=128 MMAs)
#define BN2 256            // N cols per CTA (one N=256 MMA)
#define BK2 32             // K floats per tile (128 bytes = SW128 row)
#define NT  32             // 1024 / 32 k-tiles
#define STAGES 3
#define ASZ 32768          // 256 rows * 128B
#define BSZ 32768
#define A_OFF 1024
#define B_OFF (A_OFF + STAGES * ASZ)
#define GEMM_SMEM (B_OFF + STAGES * BSZ)    // 197632 B
#define MBAR_OFF 16        // full[s] at +s*16, empty[s] at +s*16+8

// idesc: D=F32(1<<4), A=TF32(2<<7), B=TF32(2<<10), N=256 (32<<17), M=128 (8<<24)
#define IDESC_TF32 ((1u<<4) | (2u<<7) | (2u<<10) | (32u<<17) | (8u<<24))

// Scratch (device globals — allocation-free)
// A-side operands are stored BLOCKED+SWIZZLED: [mblock(64)][ktile(32)][32KB tile],
// tile layout = 256 rows x 128B with SW128 chunk swizzle (identical to smem image).
__device__ float g_xk[BATCH * DIM];
__device__ float g_xv[BATCH * DIM];
__device__ float g_xr[BATCH * DIM];
__device__ float g_K[BATCH * DIM];       // row-major
__device__ float g_V[BATCH * DIM];       // row-major
__device__ float g_R[BATCH * DIM];       // row-major
__device__ float g_rwkv[BATCH * DIM];    // blocked+swizzled
__device__ float g_Wt[4 * DIM * DIM];    // tf32, transposed [N,K], blocked+swizzled

// ---------------------------------------------------------------------------
// arch-portable helpers
// ---------------------------------------------------------------------------
__device__ __forceinline__ float tf32_rna(float x) {
    unsigned u;
    asm("cvt.rna.tf32.f32 %0, %1;" : "=r"(u) : "f"(x));
    return __uint_as_float(u);
}
__device__ __forceinline__ uint32_t smem_u32(const void* p) {
    return (uint32_t)__cvta_generic_to_shared(p);
}
__device__ __forceinline__ void mbar_init(uint32_t a, uint32_t cnt) {
    asm volatile("mbarrier.init.shared.b64 [%0], %1;" :: "r"(a), "r"(cnt) : "memory");
}
__device__ __forceinline__ void mbar_wait(uint32_t a, uint32_t parity) {
    asm volatile(
        "{\n\t.reg .pred P;\n"
        "WL%=:\n\t"
        "mbarrier.try_wait.parity.acquire.cta.shared::cta.b64 P, [%0], %1, 0x989680;\n\t"
        "@P bra WD%=;\n\t"
        "bra WL%=;\n"
        "WD%=:\n\t}"
        :: "r"(a), "r"(parity) : "memory");
}
__device__ __forceinline__ void mbar_expect_tx(uint32_t a, uint32_t bytes) {
    asm volatile("mbarrier.arrive.expect_tx.shared.b64 _, [%0], %1;"
                 :: "r"(a), "r"(bytes) : "memory");
}

// blocked+swizzled float offset for element (row, k) of a [rows,1024] operand
__device__ __forceinline__ size_t blk_off(int row, int k) {
    int mb = row >> 8, r = row & 255, kt = k >> 5, c = (k >> 2) & 7;
    return ((size_t)(mb * 32 + kt) << 13) + (size_t)(r * 32) + (size_t)(((c ^ (r & 7)) << 2) + (k & 3));
}

// ---------------------------------------------------------------------------
// tcgen05 / cluster helpers — sm_103a ONLY
// ---------------------------------------------------------------------------
#if defined(__CUDA_ARCH_FEAT_SM103_ALL) || defined(__CUDA_ARCH_FEAT_SM100_ALL)
#define HAS_TCGEN05 1
#else
#define HAS_TCGEN05 0
#endif

#if HAS_TCGEN05
__device__ __forceinline__ uint32_t elect_one() {
    uint32_t p;
    asm volatile("{\n.reg .pred P;\nelect.sync _|P, 0xFFFFFFFF;\nselp.b32 %0, 1, 0, P;\n}" : "=r"(p));
    return p;
}
__device__ __forceinline__ uint32_t ctarank() {
    uint32_t r;
    asm("mov.u32 %0, %%cluster_ctarank;" : "=r"(r));
    return r;
}
// bulk copy global->shared with cluster multicast, completion via mbarrier tx
__device__ __forceinline__ void bulk_mc(uint32_t dst, const void* src, uint32_t bytes,
                                        uint32_t mbar, uint32_t mask) {
    asm volatile(
        "cp.async.bulk.shared::cluster.global.mbarrier::complete_tx::bytes.multicast::cluster"
        " [%0], [%1], %2, [%3], %4;"
        :: "r"(dst), "l"(src), "r"(bytes), "r"(mbar), "h"((uint16_t)mask) : "memory");
}
// 64-bit smem descriptor: SW128, version=1 (Blackwell), LBO=1, SBO=64 (K-major)
__device__ __forceinline__ uint64_t make_desc(uint32_t addr) {
    const uint64_t base = (uint64_t(2) << 61) | (uint64_t(1) << 46)
                        | (uint64_t(64) << 32) | (uint64_t(1) << 16);
    return base | ((uint64_t)(addr >> 4) & 0x3FFF);
}
__device__ __forceinline__ void mma_tf32_ss(uint32_t d, uint64_t ad, uint64_t bd,
                                            uint32_t idesc, uint32_t en) {
    asm volatile(
        "{\n\t.reg .pred p;\n\t"
        "setp.ne.u32 p, %5, 0;\n\t"
        "tcgen05.mma.cta_group::1.kind::tf32 [%0], %1, %2, %3, {%4, %4, %4, %4}, p;\n\t}"
        :: "r"(d), "l"(ad), "l"(bd), "r"(idesc), "r"(0u), "r"(en) : "memory");
}
__device__ __forceinline__ void tc_commit_mc(uint32_t mbar, uint32_t mask) {
    asm volatile(
        "tcgen05.commit.cta_group::1.mbarrier::arrive::one.shared::cluster.multicast::cluster.b64 [%0], %1;"
        :: "r"(mbar), "h"((uint16_t)(mask)) : "memory");
}
#endif

// ---------------------------------------------------------------------------
// tcgen05 tf32 GEMM with 2x2 cluster multicast.
// Grid (4 N-tiles, 64 M-tiles, z), cluster (2,2,1).
//   rank = (bx&1) + 2*(by&1)
//   A tile (same M rows) shared with rank^1; B tile (same N) shared with rank^2.
// Operands are blocked+swizzled in gmem: one 16KB bulk copy per half.
// ---------------------------------------------------------------------------
__global__ void __launch_bounds__(256, 1) __cluster_dims__(2, 2, 1)
gemm_tc_kernel(const float* __restrict__ A0, const float* __restrict__ A1,
               const float* __restrict__ A2,
               const float* __restrict__ B0, const float* __restrict__ B1,
               const float* __restrict__ B2,
               float* __restrict__ C0, float* __restrict__ C1,
               float* __restrict__ C2)
{
#if HAS_TCGEN05
    const float* A;
    const float* B;
    float* C;
    if (blockIdx.z == 0)      { A = A0; B = B0; C = C0; }
    else if (blockIdx.z == 1) { A = A1; B = B1; C = C1; }
    else                      { A = A2; B = B2; C = C2; }

    extern __shared__ char smem[];
    const uint32_t sb = smem_u32(smem);

    const int tid = threadIdx.x;
    const int warp = tid >> 5;
    const int mb = blockIdx.y;            // M block (256 rows)
    const int nb = blockIdx.x;            // N block (256 cols)
    const int row0 = mb * BM2;
    const int col0 = nb * BN2;

    const uint32_t rank = ctarank();
    const uint32_t a_half = rank & 1;          // which 128-row half of A I fetch
    const uint32_t b_half = (rank >> 1) & 1;   // which 128-row half of B I fetch
    const uint32_t maskA = (1u << rank) | (1u << (rank ^ 1));
    const uint32_t maskB = (1u << rank) | (1u << (rank ^ 2));
    const uint32_t cmask = (1u << rank) | (1u << (rank ^ 1)) | (1u << (rank ^ 2));

    // TMEM alloc (512 cols): warp 0, collective
    if (warp == 0) {
        asm volatile("tcgen05.alloc.cta_group::1.sync.aligned.shared::cta.b32 [%0], %1;"
                     :: "r"(sb), "r"(512u) : "memory");
    }
    if (tid == 0) {
#pragma unroll
        for (int s = 0; s < STAGES; s++) {
            mbar_init(sb + MBAR_OFF + s * 16, 1);       // full: producer expect-arrival
            mbar_init(sb + MBAR_OFF + s * 16 + 8, 3);   // empty: 3 multicast MMA commits
        }
    }
    __syncthreads();
    uint32_t tmem;
    asm volatile("ld.shared.b32 %0, [%1];" : "=r"(tmem) : "r"(sb));

    // cluster-wide: all mbarriers initialized before any multicast targets them
    asm volatile("barrier.cluster.arrive.aligned;" ::: "memory");
    asm volatile("barrier.cluster.wait.aligned;" ::: "memory");

    if (warp == 0) {
        // ---- consumer: MMA issue ----
        if (elect_one()) {
            for (int u = 0; u < NT; u++) {
                const int st = u % STAGES;
                mbar_wait(sb + MBAR_OFF + st * 16, (uint32_t)((u / STAGES) & 1));
                uint64_t ad0 = make_desc(sb + A_OFF + st * ASZ);
                uint64_t ad1 = make_desc(sb + A_OFF + st * ASZ + 16384);
                uint64_t bd  = make_desc(sb + B_OFF + st * BSZ);
#pragma unroll
                for (int ks = 0; ks < 4; ks++) {
                    uint32_t en = (u == 0 && ks == 0) ? 0u : 1u;
                    mma_tf32_ss(tmem,       ad0 + ks * 2, bd + ks * 2, IDESC_TF32, en);
                    mma_tf32_ss(tmem + 256, ad1 + ks * 2, bd + ks * 2, IDESC_TF32, en);
                }
                tc_commit_mc(sb + MBAR_OFF + st * 16 + 8, cmask);
            }
        }
    } else if (warp == 1) {
        // ---- producer: bulk multicast loads ----
        if (elect_one()) {
            const char* Abase = (const char*)A + ((size_t)(mb * NT) << 15) + (a_half << 14);
            const char* Bbase = (const char*)B + ((size_t)(nb * NT) << 15) + (b_half << 14);
            for (int t = 0; t < NT; t++) {
                const int st = t % STAGES;
                if (t >= STAGES)
                    mbar_wait(sb + MBAR_OFF + st * 16 + 8, (uint32_t)((t / STAGES - 1) & 1));
                mbar_expect_tx(sb + MBAR_OFF + st * 16, 65536u);
                bulk_mc(sb + A_OFF + st * ASZ + a_half * 16384,
                        Abase + ((size_t)t << 15), 16384u,
                        sb + MBAR_OFF + st * 16, maskA);
                bulk_mc(sb + B_OFF + st * BSZ + b_half * 16384,
                        Bbase + ((size_t)t << 15), 16384u,
                        sb + MBAR_OFF + st * 16, maskB);
            }
        }
    }

    __syncthreads();
    // all threads: wait final MMA (tile NT-1) completion (3 commits incl. partners)
    mbar_wait(sb + MBAR_OFF + ((NT - 1) % STAGES) * 16 + 8,
              (uint32_t)(((NT - 1) / STAGES) & 1));
    asm volatile("tcgen05.fence::after_thread_sync;" ::: "memory");

    // ---- epilogue: 8 warps; warps 0-3 -> D0 (rows 0-127), 4-7 -> D1 ----
    {
        const int w = tid >> 5, lane = tid & 31;
        const uint32_t woff = (uint32_t)(w & 3) << 21;
        const uint32_t dbase = tmem + ((w >> 2) ? 256u : 0u) + woff;
        const int grow = row0 + (w >> 2) * 128 + (w & 3) * 32 + lane;
        float* crow = C + (long)grow * DIM + col0;
#pragma unroll
        for (int cb = 0; cb < 256; cb += 32) {
            uint32_t r[32];
            asm volatile(
                "tcgen05.ld.sync.aligned.32x32b.x32.b32 "
                "{%0,%1,%2,%3,%4,%5,%6,%7,%8,%9,%10,%11,%12,%13,%14,%15,"
                "%16,%17,%18,%19,%20,%21,%22,%23,%24,%25,%26,%27,%28,%29,%30,%31}, [%32];"
                : "=r"(r[0]), "=r"(r[1]), "=r"(r[2]), "=r"(r[3]),
                  "=r"(r[4]), "=r"(r[5]), "=r"(r[6]), "=r"(r[7]),
                  "=r"(r[8]), "=r"(r[9]), "=r"(r[10]), "=r"(r[11]),
                  "=r"(r[12]), "=r"(r[13]), "=r"(r[14]), "=r"(r[15]),
                  "=r"(r[16]), "=r"(r[17]), "=r"(r[18]), "=r"(r[19]),
                  "=r"(r[20]), "=r"(r[21]), "=r"(r[22]), "=r"(r[23]),
                  "=r"(r[24]), "=r"(r[25]), "=r"(r[26]), "=r"(r[27]),
                  "=r"(r[28]), "=r"(r[29]), "=r"(r[30]), "=r"(r[31])
                : "r"(dbase + cb));
            asm volatile("tcgen05.wait::ld.sync.aligned;" ::: "memory");
#pragma unroll
            for (int j = 0; j < 32; j += 4)
                *(float4*)(crow + cb + j) =
                    make_float4(__uint_as_float(r[j]), __uint_as_float(r[j + 1]),
                                __uint_as_float(r[j + 2]), __uint_as_float(r[j + 3]));
        }
    }

    __syncthreads();
    // cluster-wide quiesce before TMEM dealloc / exit
    asm volatile("barrier.cluster.arrive.aligned;" ::: "memory");
    asm volatile("barrier.cluster.wait.aligned;" ::: "memory");
    if (warp == 0) {
        asm volatile("tcgen05.relinquish_alloc_permit.cta_group::1.sync.aligned;");
        asm volatile("tcgen05.dealloc.cta_group::1.sync.aligned.b32 %0, %1;"
                     :: "r"(tmem), "r"(512u));
    }
#endif  // HAS_TCGEN05
}

// ---------------------------------------------------------------------------
// premix: xk/xv/xr = tf32( lerp(last_x, x, mix) ) written blocked+swizzled;
// also writes the x passthrough output (replaces the separate memcpy).
// ---------------------------------------------------------------------------
__global__ void __launch_bounds__(256)
premix_kernel(const float* __restrict__ x, const float* __restrict__ lx,
              const float* __restrict__ mk, const float* __restrict__ mv,
              const float* __restrict__ mr, float* __restrict__ x_out)
{
    const long i = ((long)blockIdx.x * 256 + threadIdx.x) * 4;
    const int row = (int)(i >> 10);
    const int k = (int)(i & (DIM - 1));
    const size_t off = blk_off(row, k);

    float4 xv4 = *(const float4*)(x + i);
    float4 lv4 = *(const float4*)(lx + i);
    *(float4*)(x_out + i) = xv4;

    float4 m, o;
    m = *(const float4*)(mk + k);
    o.x = tf32_rna(fmaf(xv4.x - lv4.x, m.x, lv4.x));
    o.y = tf32_rna(fmaf(xv4.y - lv4.y, m.y, lv4.y));
    o.z = tf32_rna(fmaf(xv4.z - lv4.z, m.z, lv4.z));
    o.w = tf32_rna(fmaf(xv4.w - lv4.w, m.w, lv4.w));
    *(float4*)(g_xk + off) = o;

    m = *(const float4*)(mv + k);
    o.x = tf32_rna(fmaf(xv4.x - lv4.x, m.x, lv4.x));
    o.y = tf32_rna(fmaf(xv4.y - lv4.y, m.y, lv4.y));
    o.z = tf32_rna(fmaf(xv4.z - lv4.z, m.z, lv4.z));
    o.w = tf32_rna(fmaf(xv4.w - lv4.w, m.w, lv4.w));
    *(float4*)(g_xv + off) = o;

    m = *(const float4*)(mr + k);
    o.x = tf32_rna(fmaf(xv4.x - lv4.x, m.x, lv4.x));
    o.y = tf32_rna(fmaf(xv4.y - lv4.y, m.y, lv4.y));
    o.z = tf32_rna(fmaf(xv4.z - lv4.z, m.z, lv4.z));
    o.w = tf32_rna(fmaf(xv4.w - lv4.w, m.w, lv4.w));
    *(float4*)(g_xr + off) = o;
}

// ---------------------------------------------------------------------------
// weight convert + transpose into blocked+swizzled [N,K] layout
// ---------------------------------------------------------------------------
__global__ void __launch_bounds__(256)
cvtw_kernel(const float* __restrict__ Wk, const float* __restrict__ Wv,
            const float* __restrict__ Wr, const float* __restrict__ Wout)
{
    __shared__ float t[32][33];
    const float* src;
    if (blockIdx.z == 0)      src = Wk;
    else if (blockIdx.z == 1) src = Wv;
    else if (blockIdx.z == 2) src = Wr;
    else                      src = Wout;
    float* dst = g_Wt + (size_t)blockIdx.z * DIM * DIM;

    const int kb = blockIdx.x * 32, nb = blockIdx.y * 32;
    const int tx = threadIdx.x & 31, ty = threadIdx.x >> 5;   // 32 x 8
#pragma unroll
    for (int r = ty; r < 32; r += 8)
        t[r][tx] = tf32_rna(src[(long)(kb + r) * DIM + nb + tx]);
    __syncthreads();
#pragma unroll
    for (int r = ty; r < 32; r += 8)
        dst[blk_off(nb + r, kb + tx)] = t[tx][r];
}

// ---------------------------------------------------------------------------
// elementwise RWKV recurrence (reads row-major K/V/R; writes rwkv blocked)
// ---------------------------------------------------------------------------
__global__ void __launch_bounds__(256)
rwkv_ew_kernel(const float* __restrict__ last_num, const float* __restrict__ last_den,
               const float* __restrict__ decay, const float* __restrict__ bonus,
               float* __restrict__ num_out, float* __restrict__ den_out)
{
    const long i = ((long)blockIdx.x * 256 + threadIdx.x) * 4;
    const int row = (int)(i >> 10);
    const int a = (int)(i & (DIM - 1));

    float4 kk = *(const float4*)(g_K + i);
    float4 vv = *(const float4*)(g_V + i);
    float4 rp = *(const float4*)(g_R + i);
    float4 ln = *(const float4*)(last_num + i);
    float4 ld = *(const float4*)(last_den + i);
    float4 bo = *(const float4*)(bonus + a);
    float4 de = *(const float4*)(decay + a);

    float4 rw, no, dn;
    {
        const float* kp = &kk.x; const float* vp = &vv.x; const float* rpp = &rp.x;
        const float* lnp = &ln.x; const float* ldp = &ld.x;
        const float* bop = &bo.x; const float* dep = &de.x;
        float* rwp = &rw.x; float* nop = &no.x; float* dnp = &dn.x;
#pragma unroll
        for (int t = 0; t < 4; t++) {
            float k = kp[t], v = vp[t];
            float ebk = expf(bop[t] + k);
            float wkv = (lnp[t] + ebk * v) / (ldp[t] + ebk);
            float r = 1.0f / (1.0f + expf(-rpp[t]));
            rwp[t] = tf32_rna(r * wkv);
            float w = expf(-expf(dep[t]));
            float ek = expf(k);
            nop[t] = w * lnp[t] + ek * v;
            dnp[t] = w * ldp[t] + ek;
        }
    }
    *(float4*)(g_rwkv + blk_off(row, a)) = rw;
    *(float4*)(num_out + i) = no;
    *(float4*)(den_out + i) = dn;
}

// ---------------------------------------------------------------------------
// Launch
// ---------------------------------------------------------------------------
extern "C" void kernel_launch(void* const* d_in, const int* in_sizes, int n_in,
                              void* d_out, int out_size)
{
    const float* x        = (const float*)d_in[0];
    const float* last_x   = (const float*)d_in[1];
    const float* last_num = (const float*)d_in[2];
    const float* last_den = (const float*)d_in[3];
    const float* mix_k    = (const float*)d_in[4];
    const float* mix_v    = (const float*)d_in[5];
    const float* mix_r    = (const float*)d_in[6];
    const float* decay    = (const float*)d_in[7];
    const float* bonus    = (const float*)d_in[8];
    const float* Wk       = (const float*)d_in[9];
    const float* Wv       = (const float*)d_in[10];
    const float* Wr       = (const float*)d_in[11];
    const float* Wout     = (const float*)d_in[12];

    float* out = (float*)d_out;
    const long BD = (long)BATCH * DIM;
    float* hidden_out = out;
    float* x_out      = out + BD;
    float* num_out    = out + 2 * BD;
    float* den_out    = out + 3 * BD;

    static bool attr_set = false;
    if (!attr_set) {
        cudaFuncSetAttribute(gemm_tc_kernel,
                             cudaFuncAttributeMaxDynamicSharedMemorySize, GEMM_SMEM);
        attr_set = true;
    }

    float *p_xk, *p_xv, *p_xr, *p_K, *p_V, *p_R, *p_rwkv, *p_Wt;
    cudaGetSymbolAddress((void**)&p_xk, g_xk);
    cudaGetSymbolAddress((void**)&p_xv, g_xv);
    cudaGetSymbolAddress((void**)&p_xr, g_xr);
    cudaGetSymbolAddress((void**)&p_K, g_K);
    cudaGetSymbolAddress((void**)&p_V, g_V);
    cudaGetSymbolAddress((void**)&p_R, g_R);
    cudaGetSymbolAddress((void**)&p_rwkv, g_rwkv);
    cudaGetSymbolAddress((void**)&p_Wt, g_Wt);

    // 1) premix (also writes x passthrough)
    premix_kernel<<<(unsigned)(BD / 4 / 256), 256>>>(x, last_x, mix_k, mix_v, mix_r, x_out);

    // 2) weight convert+transpose into blocked layout (tiny)
    dim3 gw(DIM / 32, DIM / 32, 4);
    cvtw_kernel<<<gw, 256>>>(Wk, Wv, Wr, Wout);

    // 3) K/V/R projections
    dim3 grid1(DIM / BN2, BATCH / BM2, 3);
    gemm_tc_kernel<<<grid1, 256, GEMM_SMEM>>>(
        p_xk, p_xv, p_xr,
        p_Wt + 0L * DIM * DIM, p_Wt + 1L * DIM * DIM, p_Wt + 2L * DIM * DIM,
        p_K, p_V, p_R);

    // 4) elementwise recurrence
    rwkv_ew_kernel<<<(unsigned)(BD / 4 / 256), 256>>>(last_num, last_den, decay, bonus,
                                                      num_out, den_out);

    // 5) hidden = rwkv @ Wout
    dim3 grid2(DIM / BN2, BATCH / BM2, 1);
    gemm_tc_kernel<<<grid2, 256, GEMM_SMEM>>>(
        p_rwkv, p_rwkv, p_rwkv,
        p_Wt + 3L * DIM * DIM, p_Wt + 3L * DIM * DIM, p_Wt + 3L * DIM * DIM,
        hidden_out, hidden_out, hidden_out);
}